// round 1
// baseline (speedup 1.0000x reference)
#include <cuda_runtime.h>
#include <cuda_bf16.h>
#include <cstdint>
#include <math.h>

// ---------------------------------------------------------------------------
// RoiProposal: RPN proposal layer (softmax -> box decode -> top6000 -> NMS -> top300)
// ---------------------------------------------------------------------------

#define NPROP 36864      // 64*64*9 anchors
#define NSORT 65536      // padded sort size
#define KTOP  6000       // PRE_NMS_TOPN
#define KPAD  6016       // KTOP padded to multiple of 32
#define WORDS 188        // KPAD/32
#define TILES 188
#define NOUT  300

// ------------------------------ scratch (static, allocation-free) -----------
__device__ uint64_t g_keys[NSORT];
__device__ float g_px1[NPROP], g_py1[NPROP], g_px2[NPROP], g_py2[NPROP];
__device__ float g_tx1[KPAD], g_ty1[KPAD], g_tx2[KPAD], g_ty2[KPAD], g_ta[KPAD];
__device__ unsigned g_maskT[(size_t)WORDS * KPAD];   // column-word-major: [word][row]
__device__ unsigned g_removed[WORDS];

// base anchor widths/heights (py-faster-rcnn generate_anchors, exact integers)
__constant__ float c_AW[9] = {184.f, 368.f, 736.f, 128.f, 256.f, 512.f, 88.f, 176.f, 352.f};
__constant__ float c_AH[9] = {96.f, 192.f, 384.f, 128.f, 256.f, 512.f, 176.f, 352.f, 704.f};

// ------------------------------ 1) proposals + sort keys --------------------
__global__ void proposal_kernel(const float* __restrict__ cls,
                                const float* __restrict__ bbox) {
    int i = blockIdx.x * blockDim.x + threadIdx.x;
    if (i >= NSORT) return;
    if (i >= NPROP) { g_keys[i] = 0ull; return; }

    int a = i % 9;
    int cell = i / 9;
    float axc = (float)((cell % 64) * 16 + 8);   // exact: shift_x + 8
    float ayc = (float)((cell / 64) * 16 + 8);
    float aw = c_AW[a];
    float ah = c_AH[a];

    const float* cp = cls + cell * 18 + a * 2;
    float s0 = cp[0], s1 = cp[1];
    const float* dp = bbox + cell * 36 + a * 4;
    float dx = dp[0], dy = dp[1], dw = dp[2], dh = dp[3];

    // box decode — explicit .rn ops (no FMA contraction; match XLA codegen)
    float pxc = __fadd_rn(__fmul_rn(dx, aw), axc);
    float pyc = __fadd_rn(__fmul_rn(dy, ah), ayc);
    float pw  = __fmul_rn(expf(dw), aw);
    float ph  = __fmul_rn(expf(dh), ah);
    float hx  = __fmul_rn(0.5f, pw);
    float hy  = __fmul_rn(0.5f, ph);
    float x1 = fminf(fmaxf(__fsub_rn(pxc, hx), 0.f), 1023.f);
    float x2 = fminf(fmaxf(__fadd_rn(pxc, hx), 0.f), 1023.f);
    float y1 = fminf(fmaxf(__fsub_rn(pyc, hy), 0.f), 1023.f);
    float y2 = fminf(fmaxf(__fadd_rn(pyc, hy), 0.f), 1023.f);

    bool valid = (__fadd_rn(__fsub_rn(x2, x1), 1.f) >= 16.f) &&
                 (__fadd_rn(__fsub_rn(y2, y1), 1.f) >= 16.f);

    // softmax([s0,s1])[1], max-subtracted exactly like jax.nn.softmax
    float m  = fmaxf(s0, s1);
    float e0 = expf(__fsub_rn(s0, m));
    float e1 = expf(__fsub_rn(s1, m));
    float sc = __fdiv_rn(e1, __fadd_rn(e0, e1));
    if (!valid) sc = -INFINITY;

    g_px1[i] = x1; g_py1[i] = y1; g_px2[i] = x2; g_py2[i] = y2;

    // monotonic float->uint, key = score<<32 | (~index) -> desc sort == (score desc, idx asc)
    unsigned ub = __float_as_uint(sc);
    ub = (ub & 0x80000000u) ? ~ub : (ub | 0x80000000u);
    g_keys[i] = ((uint64_t)ub << 32) | (uint64_t)(0xFFFFFFFFu - (unsigned)i);
}

// ------------------------------ 2) bitonic sort (descending) ----------------
// chunk = 4096 elems (32KB static smem), 512 threads/block
__device__ __forceinline__ void cmpswap_s(uint64_t* s, int i, int j, bool desc) {
    uint64_t a = s[i], b = s[i | j];
    if (desc ? (a < b) : (a > b)) { s[i] = b; s[i | j] = a; }
}

__global__ void local_sort_kernel() {
    __shared__ uint64_t s[4096];
    int base = blockIdx.x * 4096;
    for (int e = threadIdx.x; e < 4096; e += 512) s[e] = g_keys[base + e];
    __syncthreads();
    for (int k = 2; k <= 4096; k <<= 1) {
        for (int j = k >> 1; j > 0; j >>= 1) {
            for (int tt = threadIdx.x; tt < 2048; tt += 512) {
                int i = ((tt & ~(j - 1)) << 1) | (tt & (j - 1));
                bool desc = (((base + i) & k) == 0);
                cmpswap_s(s, i, j, desc);
            }
            __syncthreads();
        }
    }
    for (int e = threadIdx.x; e < 4096; e += 512) g_keys[base + e] = s[e];
}

__global__ void global_pass_kernel(int k, int j) {
    int tt = blockIdx.x * blockDim.x + threadIdx.x;
    if (tt >= NSORT / 2) return;
    int i = ((tt & ~(j - 1)) << 1) | (tt & (j - 1));
    bool desc = ((i & k) == 0);
    uint64_t a = g_keys[i], b = g_keys[i | j];
    if (desc ? (a < b) : (a > b)) { g_keys[i] = b; g_keys[i | j] = a; }
}

__global__ void local_merge_kernel(int k) {
    __shared__ uint64_t s[4096];
    int base = blockIdx.x * 4096;
    for (int e = threadIdx.x; e < 4096; e += 512) s[e] = g_keys[base + e];
    __syncthreads();
    for (int j = 2048; j > 0; j >>= 1) {
        for (int tt = threadIdx.x; tt < 2048; tt += 512) {
            int i = ((tt & ~(j - 1)) << 1) | (tt & (j - 1));
            bool desc = (((base + i) & k) == 0);
            cmpswap_s(s, i, j, desc);
        }
        __syncthreads();
    }
    for (int e = threadIdx.x; e < 4096; e += 512) g_keys[base + e] = s[e];
}

// ------------------------------ 3) gather top-6000 boxes (SoA) --------------
__global__ void gather_kernel() {
    int k = blockIdx.x * blockDim.x + threadIdx.x;
    if (k >= KPAD) return;
    if (k < KTOP) {
        uint64_t key = g_keys[k];
        unsigned idx = 0xFFFFFFFFu - (unsigned)(key & 0xFFFFFFFFull);
        float x1 = g_px1[idx], y1 = g_py1[idx], x2 = g_px2[idx], y2 = g_py2[idx];
        g_tx1[k] = x1; g_ty1[k] = y1; g_tx2[k] = x2; g_ty2[k] = y2;
        g_ta[k] = __fmul_rn(__fadd_rn(__fsub_rn(x2, x1), 1.f),
                            __fadd_rn(__fsub_rn(y2, y1), 1.f));
    } else {
        g_tx1[k] = -1e8f; g_ty1[k] = -1e8f; g_tx2[k] = -1e8f; g_ty2[k] = -1e8f;
        g_ta[k] = 1.f;
    }
}

// ------------------------------ 4) IoU suppression bitmask ------------------
// bit j of word[wx][row]: (col = wx*32+j) suppressible by row (iou>0.7, col>row)
__global__ void mask_kernel() {
    int wx = blockIdx.x;                       // 0..187
    int r  = blockIdx.y * 128 + threadIdx.x;   // 0..6015
    __shared__ float sx1[32], sy1[32], sx2[32], sy2[32], sa[32];
    if (threadIdx.x < 32) {
        int c = wx * 32 + threadIdx.x;
        sx1[threadIdx.x] = g_tx1[c]; sy1[threadIdx.x] = g_ty1[c];
        sx2[threadIdx.x] = g_tx2[c]; sy2[threadIdx.x] = g_ty2[c];
        sa[threadIdx.x]  = g_ta[c];
    }
    __syncthreads();
    unsigned w = 0;
    if (r < KTOP) {
        float x1 = g_tx1[r], y1 = g_ty1[r], x2 = g_tx2[r], y2 = g_ty2[r], ar = g_ta[r];
        #pragma unroll
        for (int b = 0; b < 32; b++) {
            int c = wx * 32 + b;
            float ix1 = fmaxf(x1, sx1[b]);
            float iy1 = fmaxf(y1, sy1[b]);
            float ix2 = fminf(x2, sx2[b]);
            float iy2 = fminf(y2, sy2[b]);
            float iw = fmaxf(__fadd_rn(__fsub_rn(ix2, ix1), 1.f), 0.f);
            float ih = fmaxf(__fadd_rn(__fsub_rn(iy2, iy1), 1.f), 0.f);
            float inter = __fmul_rn(iw, ih);
            float uni = __fsub_rn(__fadd_rn(ar, sa[b]), inter);
            float iou = __fdiv_rn(inter, uni);
            bool bit = (c > r) && (c < KTOP) && (iou > 0.7f);
            w |= ((unsigned)bit) << b;
        }
    }
    if (r < KPAD) g_maskT[(size_t)wx * KPAD + r] = w;
}

// ------------------------------ 5) sequential greedy scan (exact) -----------
// Single block, 192 threads. Thread t owns removed-word t (cols 32t..32t+31).
// Per 32-row tile: owner thread resolves the diagonal block serially in regs,
// then everyone ORs kept rows into their removed word. One sync per tile.
__global__ void nms_scan_kernel() {
    int t = threadIdx.x;
    __shared__ unsigned s_keep[TILES];
    unsigned removed = 0;
    for (int T = 0; T < TILES; T++) {
        unsigned roww[32];
        if (t < WORDS) {
            const uint4* q = reinterpret_cast<const uint4*>(
                &g_maskT[(size_t)t * KPAD + T * 32]);
            #pragma unroll
            for (int b8 = 0; b8 < 8; b8++) {
                uint4 v = q[b8];
                roww[4 * b8 + 0] = v.x; roww[4 * b8 + 1] = v.y;
                roww[4 * b8 + 2] = v.z; roww[4 * b8 + 3] = v.w;
            }
        }
        if (t == T) {
            unsigned internal = removed;   // external suppression for this tile's rows
            unsigned keptbits = 0;
            #pragma unroll
            for (int b = 0; b < 32; b++) {
                if (((internal >> b) & 1u) == 0u) {
                    keptbits |= (1u << b);
                    internal |= roww[b];
                }
            }
            s_keep[T] = keptbits;
        }
        __syncthreads();
        unsigned km = s_keep[T];
        if (t < WORDS) {
            unsigned a0 = 0, a1 = 0, a2 = 0, a3 = 0;
            #pragma unroll
            for (int b = 0; b < 32; b += 4) {
                a0 |= (km & (1u << b))       ? roww[b]     : 0u;
                a1 |= (km & (1u << (b + 1))) ? roww[b + 1] : 0u;
                a2 |= (km & (1u << (b + 2))) ? roww[b + 2] : 0u;
                a3 |= (km & (1u << (b + 3))) ? roww[b + 3] : 0u;
            }
            removed |= (a0 | a1) | (a2 | a3);
        }
    }
    if (t < WORDS) g_removed[t] = removed;
}

// ------------------------------ 6) select first 300 + write output ----------
__global__ void select_kernel(float* __restrict__ out) {
    int t = threadIdx.x;    // 192 threads
    __shared__ int s[192];
    __shared__ int sidx[NOUT];

    unsigned vmask = (t < WORDS) ? ((t == WORDS - 1) ? 0x0000FFFFu : 0xFFFFFFFFu) : 0u;
    unsigned rem  = (t < WORDS) ? g_removed[t] : 0u;
    unsigned kept = (~rem) & vmask;
    int cnt = __popc(kept);

    // inclusive scan (Hillis-Steele)
    s[t] = cnt; __syncthreads();
    for (int off = 1; off < 192; off <<= 1) {
        int v = (t >= off) ? s[t - off] : 0;
        __syncthreads();
        s[t] += v;
        __syncthreads();
    }
    int excl = s[t] - cnt;
    int C = s[191];

    if (excl < NOUT && kept) {
        int r = excl;
        #pragma unroll 4
        for (int b = 0; b < 32; b++) {
            if ((kept >> b) & 1u) {
                if (r < NOUT) sidx[r] = t * 32 + b;
                r++;
            }
        }
    }
    __syncthreads();

    if (C < NOUT) {  // fill with suppressed boxes, index ascending (ties at -inf)
        unsigned sup = rem & vmask;
        int cnt2 = __popc(sup);
        s[t] = cnt2; __syncthreads();
        for (int off = 1; off < 192; off <<= 1) {
            int v = (t >= off) ? s[t - off] : 0;
            __syncthreads();
            s[t] += v;
            __syncthreads();
        }
        int base = C + (s[t] - cnt2);
        if (base < NOUT && sup) {
            #pragma unroll 4
            for (int b = 0; b < 32; b++) {
                if ((sup >> b) & 1u) {
                    if (base < NOUT) sidx[base] = t * 32 + b;
                    base++;
                }
            }
        }
        __syncthreads();
    }

    for (int r = t; r < NOUT; r += 192) {
        int idx = sidx[r];
        out[5 * r + 0] = 0.f;
        out[5 * r + 1] = g_tx1[idx];
        out[5 * r + 2] = g_ty1[idx];
        out[5 * r + 3] = g_tx2[idx];
        out[5 * r + 4] = g_ty2[idx];
    }
}

// ------------------------------ launch --------------------------------------
extern "C" void kernel_launch(void* const* d_in, const int* in_sizes, int n_in,
                              void* d_out, int out_size) {
    const float* cls  = (const float*)d_in[0];   // (1,64,64,18)
    const float* bbox = (const float*)d_in[1];   // (1,64,64,36)
    float* out = (float*)d_out;                  // (300,5)

    // 1) proposals + keys
    proposal_kernel<<<NSORT / 256, 256>>>(cls, bbox);

    // 2) bitonic sort, descending, 65536 keys
    local_sort_kernel<<<NSORT / 4096, 512>>>();
    for (int k = 8192; k <= NSORT; k <<= 1) {
        for (int j = k >> 1; j >= 4096; j >>= 1) {
            global_pass_kernel<<<(NSORT / 2) / 256, 256>>>(k, j);
        }
        local_merge_kernel<<<NSORT / 4096, 512>>>(k);
    }

    // 3) gather top-6000 boxes
    gather_kernel<<<KPAD / 128, 128>>>();

    // 4) suppression bitmask
    dim3 mg(WORDS, KPAD / 128);
    mask_kernel<<<mg, 128>>>();

    // 5) exact greedy NMS scan
    nms_scan_kernel<<<1, 192>>>();

    // 6) select + output
    select_kernel<<<1, 192>>>(out);
}

// round 2
// speedup vs baseline: 3.2085x; 3.2085x over previous
#include <cuda_runtime.h>
#include <cuda_bf16.h>
#include <cub/cub.cuh>
#include <cstdint>
#include <math.h>

// ---------------------------------------------------------------------------
// RoiProposal: RPN proposal layer (softmax -> box decode -> top6000 -> NMS -> top300)
// ---------------------------------------------------------------------------

#define NPROP 36864      // 64*64*9 anchors
#define KTOP  6000       // PRE_NMS_TOPN
#define KPAD  6016       // KTOP padded to multiple of 32
#define WORDS 188        // KPAD/32
#define TILES 188
#define NOUT  300

// ------------------------------ scratch (static, allocation-free) -----------
__device__ unsigned g_skey[NPROP];      // monotonic score keys
__device__ unsigned g_sidx[NPROP];      // 0..NPROP-1
__device__ unsigned g_skey_out[NPROP];
__device__ unsigned g_sidx_out[NPROP];
__device__ unsigned char g_temp[4 << 20];   // cub temp storage (4 MB, >> needed)

__device__ float g_px1[NPROP], g_py1[NPROP], g_px2[NPROP], g_py2[NPROP];
__device__ float g_tx1[KPAD], g_ty1[KPAD], g_tx2[KPAD], g_ty2[KPAD], g_ta[KPAD];
__device__ unsigned g_maskT[(size_t)WORDS * KPAD];   // column-word-major: [word][row]
__device__ unsigned g_removed[WORDS];
__device__ int g_stoptile;

// base anchor widths/heights (py-faster-rcnn generate_anchors, exact integers)
__constant__ float c_AW[9] = {184.f, 368.f, 736.f, 128.f, 256.f, 512.f, 88.f, 176.f, 352.f};
__constant__ float c_AH[9] = {96.f, 192.f, 384.f, 128.f, 256.f, 512.f, 176.f, 352.f, 704.f};

// ------------------------------ 1) proposals + sort keys --------------------
__global__ void proposal_kernel(const float* __restrict__ cls,
                                const float* __restrict__ bbox) {
    int i = blockIdx.x * blockDim.x + threadIdx.x;
    if (i >= NPROP) return;

    int a = i % 9;
    int cell = i / 9;
    float axc = (float)((cell % 64) * 16 + 8);
    float ayc = (float)((cell / 64) * 16 + 8);
    float aw = c_AW[a];
    float ah = c_AH[a];

    const float* cp = cls + cell * 18 + a * 2;
    float s0 = cp[0], s1 = cp[1];
    const float* dp = bbox + cell * 36 + a * 4;
    float dx = dp[0], dy = dp[1], dw = dp[2], dh = dp[3];

    // box decode — explicit .rn ops (no FMA contraction; match XLA codegen)
    float pxc = __fadd_rn(__fmul_rn(dx, aw), axc);
    float pyc = __fadd_rn(__fmul_rn(dy, ah), ayc);
    float pw  = __fmul_rn(expf(dw), aw);
    float ph  = __fmul_rn(expf(dh), ah);
    float hx  = __fmul_rn(0.5f, pw);
    float hy  = __fmul_rn(0.5f, ph);
    float x1 = fminf(fmaxf(__fsub_rn(pxc, hx), 0.f), 1023.f);
    float x2 = fminf(fmaxf(__fadd_rn(pxc, hx), 0.f), 1023.f);
    float y1 = fminf(fmaxf(__fsub_rn(pyc, hy), 0.f), 1023.f);
    float y2 = fminf(fmaxf(__fadd_rn(pyc, hy), 0.f), 1023.f);

    bool valid = (__fadd_rn(__fsub_rn(x2, x1), 1.f) >= 16.f) &&
                 (__fadd_rn(__fsub_rn(y2, y1), 1.f) >= 16.f);

    float m  = fmaxf(s0, s1);
    float e0 = expf(__fsub_rn(s0, m));
    float e1 = expf(__fsub_rn(s1, m));
    float sc = __fdiv_rn(e1, __fadd_rn(e0, e1));
    if (!valid) sc = -INFINITY;

    g_px1[i] = x1; g_py1[i] = y1; g_px2[i] = x2; g_py2[i] = y2;

    // monotonic float->uint; stable descending radix sort => (score desc, idx asc)
    unsigned ub = __float_as_uint(sc);
    ub = (ub & 0x80000000u) ? ~ub : (ub | 0x80000000u);
    g_skey[i] = ub;
    g_sidx[i] = (unsigned)i;
}

// ------------------------------ 2) gather top-6000 boxes (SoA) --------------
__global__ void gather_kernel() {
    int k = blockIdx.x * blockDim.x + threadIdx.x;
    if (k >= KPAD) return;
    if (k < KTOP) {
        unsigned idx = g_sidx_out[k];
        float x1 = g_px1[idx], y1 = g_py1[idx], x2 = g_px2[idx], y2 = g_py2[idx];
        g_tx1[k] = x1; g_ty1[k] = y1; g_tx2[k] = x2; g_ty2[k] = y2;
        g_ta[k] = __fmul_rn(__fadd_rn(__fsub_rn(x2, x1), 1.f),
                            __fadd_rn(__fsub_rn(y2, y1), 1.f));
    } else {
        g_tx1[k] = -1e8f; g_ty1[k] = -1e8f; g_tx2[k] = -1e8f; g_ty2[k] = -1e8f;
        g_ta[k] = 1.f;
    }
}

// ------------------------------ 3) IoU suppression bitmask ------------------
// bit j of word[wx][row]: (col = wx*32+j) suppressible by row (iou>0.7, col>row)
// Blocks entirely below the diagonal (never read by the scan) exit immediately.
__global__ void mask_kernel() {
    int wx = blockIdx.x;                       // 0..187
    if (wx < 4 * (int)blockIdx.y) return;      // word never read for these rows
    int r  = blockIdx.y * 128 + threadIdx.x;   // 0..6015
    __shared__ float sx1[32], sy1[32], sx2[32], sy2[32], sa[32];
    if (threadIdx.x < 32) {
        int c = wx * 32 + threadIdx.x;
        sx1[threadIdx.x] = g_tx1[c]; sy1[threadIdx.x] = g_ty1[c];
        sx2[threadIdx.x] = g_tx2[c]; sy2[threadIdx.x] = g_ty2[c];
        sa[threadIdx.x]  = g_ta[c];
    }
    __syncthreads();
    unsigned w = 0;
    if (r < KTOP) {
        float x1 = g_tx1[r], y1 = g_ty1[r], x2 = g_tx2[r], y2 = g_ty2[r], ar = g_ta[r];
        #pragma unroll
        for (int b = 0; b < 32; b++) {
            int c = wx * 32 + b;
            float ix1 = fmaxf(x1, sx1[b]);
            float iy1 = fmaxf(y1, sy1[b]);
            float ix2 = fminf(x2, sx2[b]);
            float iy2 = fminf(y2, sy2[b]);
            float iw = fmaxf(__fadd_rn(__fsub_rn(ix2, ix1), 1.f), 0.f);
            float ih = fmaxf(__fadd_rn(__fsub_rn(iy2, iy1), 1.f), 0.f);
            float inter = __fmul_rn(iw, ih);
            float uni = __fsub_rn(__fadd_rn(ar, sa[b]), inter);
            float iou = __fdiv_rn(inter, uni);
            bool bit = (c > r) && (c < KTOP) && (iou > 0.7f);
            w |= ((unsigned)bit) << b;
        }
    }
    if (r < KPAD) g_maskT[(size_t)wx * KPAD + r] = w;
}

// ------------------------------ 4) sequential greedy scan (exact) -----------
__device__ __forceinline__ void load_tile(unsigned (&dst)[32], int t, int T) {
    const uint4* q = reinterpret_cast<const uint4*>(
        &g_maskT[(size_t)t * KPAD + (size_t)T * 32]);
    #pragma unroll
    for (int i = 0; i < 8; i++) {
        uint4 v = q[i];
        dst[4*i+0] = v.x; dst[4*i+1] = v.y; dst[4*i+2] = v.z; dst[4*i+3] = v.w;
    }
}

__device__ __forceinline__ unsigned or_sel(const unsigned (&w)[32], unsigned km) {
    unsigned a0 = 0, a1 = 0, a2 = 0, a3 = 0;
    #pragma unroll
    for (int b = 0; b < 32; b += 4) {
        if (km & (1u << b))       a0 |= w[b];
        if (km & (1u << (b + 1))) a1 |= w[b + 1];
        if (km & (1u << (b + 2))) a2 |= w[b + 2];
        if (km & (1u << (b + 3))) a3 |= w[b + 3];
    }
    return (a0 | a1) | (a2 | a3);
}

__device__ __forceinline__ void diag_resolve(const unsigned (&D)[32], unsigned removed,
                                             unsigned& kept_out) {
    unsigned internal = removed, kept = 0u;
    #pragma unroll
    for (int b = 0; b < 32; b++) {
        if (!((internal >> b) & 1u)) { kept |= (1u << b); internal |= D[b]; }
    }
    kept_out = kept;
}

// Single block, 192 threads. Thread t owns removed-word t (cols 32t..32t+31).
// Diagonal blocks preloaded to regs; OR-stage data double-buffered w/ distance-1
// prefetch; one __syncthreads per tile; early stop once >= 300 boxes kept.
__global__ void nms_scan_kernel() {
    int t = threadIdx.x;
    bool act = (t < WORDS);
    __shared__ unsigned s_keep[2];
    __shared__ int s_tot[2];
    unsigned D[32], A[32], B[32];
    unsigned removed = 0;

    if (act) load_tile(D, t, t);           // own diagonal block
    if (act && t >= 1) load_tile(A, t, 0); // tile 0 data (t==0 uses D)

    int stop = TILES - 1;
    #pragma unroll 1
    for (int T = 0; T < TILES; T += 2) {
        // ---- even tile T (cur = A) ----
        if (act && t >= T + 2 && T + 1 < TILES) load_tile(B, t, T + 1);
        if (t == T) {
            unsigned kept;
            diag_resolve(D, removed, kept);
            s_keep[0] = kept;
            unsigned cv = (T == TILES - 1) ? (kept & 0xFFFFu) : kept;
            s_tot[0] = ((T == 0) ? 0 : s_tot[1]) + __popc(cv);
        }
        __syncthreads();
        {
            unsigned km = s_keep[0];
            if (act && t >= T) {
                if (t == T) removed |= or_sel(D, km);
                else        removed |= or_sel(A, km);
            }
            if (s_tot[0] >= NOUT) { stop = T; break; }
        }
        // ---- odd tile T+1 (cur = B) ----
        if (T + 1 < TILES) {
            if (act && t >= T + 3 && T + 2 < TILES) load_tile(A, t, T + 2);
            if (t == T + 1) {
                unsigned kept;
                diag_resolve(D, removed, kept);
                s_keep[1] = kept;
                unsigned cv = (T + 1 == TILES - 1) ? (kept & 0xFFFFu) : kept;
                s_tot[1] = s_tot[0] + __popc(cv);
            }
            __syncthreads();
            unsigned km = s_keep[1];
            if (act && t >= T + 1) {
                if (t == T + 1) removed |= or_sel(D, km);
                else            removed |= or_sel(B, km);
            }
            if (s_tot[1] >= NOUT) { stop = T + 1; break; }
        }
    }
    if (act) g_removed[t] = removed;
    if (t == 0) g_stoptile = stop;
}

// ------------------------------ 5) select first 300 + write output ----------
__global__ void select_kernel(float* __restrict__ out) {
    int t = threadIdx.x;    // 192 threads
    __shared__ int s[192];
    __shared__ int sidx[NOUT];

    int L = min(KTOP, 32 * (g_stoptile + 1));   // rows with finalized status
    int nb = L - 32 * t;
    nb = nb < 0 ? 0 : (nb > 32 ? 32 : nb);
    unsigned vmask = (nb >= 32) ? 0xFFFFFFFFu : ((nb > 0) ? ((1u << nb) - 1u) : 0u);

    unsigned rem  = (t < WORDS) ? g_removed[t] : 0u;
    unsigned kept = (~rem) & vmask;
    int cnt = __popc(kept);

    // inclusive scan (Hillis-Steele)
    s[t] = cnt; __syncthreads();
    for (int off = 1; off < 192; off <<= 1) {
        int v = (t >= off) ? s[t - off] : 0;
        __syncthreads();
        s[t] += v;
        __syncthreads();
    }
    int excl = s[t] - cnt;
    int C = s[191];

    if (excl < NOUT && kept) {
        int r = excl;
        #pragma unroll 4
        for (int b = 0; b < 32; b++) {
            if ((kept >> b) & 1u) {
                if (r < NOUT) sidx[r] = t * 32 + b;
                r++;
            }
        }
    }
    __syncthreads();

    if (C < NOUT) {  // only possible after a full scan; fill with suppressed, idx asc
        unsigned sup = rem & vmask;
        int cnt2 = __popc(sup);
        s[t] = cnt2; __syncthreads();
        for (int off = 1; off < 192; off <<= 1) {
            int v = (t >= off) ? s[t - off] : 0;
            __syncthreads();
            s[t] += v;
            __syncthreads();
        }
        int base = C + (s[t] - cnt2);
        if (base < NOUT && sup) {
            #pragma unroll 4
            for (int b = 0; b < 32; b++) {
                if ((sup >> b) & 1u) {
                    if (base < NOUT) sidx[base] = t * 32 + b;
                    base++;
                }
            }
        }
        __syncthreads();
    }

    for (int r = t; r < NOUT; r += 192) {
        int idx = sidx[r];
        out[5 * r + 0] = 0.f;
        out[5 * r + 1] = g_tx1[idx];
        out[5 * r + 2] = g_ty1[idx];
        out[5 * r + 3] = g_tx2[idx];
        out[5 * r + 4] = g_ty2[idx];
    }
}

// ------------------------------ launch --------------------------------------
extern "C" void kernel_launch(void* const* d_in, const int* in_sizes, int n_in,
                              void* d_out, int out_size) {
    const float* cls  = (const float*)d_in[0];   // (1,64,64,18)
    const float* bbox = (const float*)d_in[1];   // (1,64,64,36)
    float* out = (float*)d_out;                  // (300,5)

    // 1) proposals + keys
    proposal_kernel<<<(NPROP + 255) / 256, 256>>>(cls, bbox);

    // 2) stable descending radix sort (score desc, index asc) via cub
    unsigned *kin, *kout, *vin, *vout;
    void* tmp;
    cudaGetSymbolAddress((void**)&kin,  g_skey);
    cudaGetSymbolAddress((void**)&kout, g_skey_out);
    cudaGetSymbolAddress((void**)&vin,  g_sidx);
    cudaGetSymbolAddress((void**)&vout, g_sidx_out);
    cudaGetSymbolAddress(&tmp, g_temp);
    size_t temp_bytes = sizeof(g_temp);
    cub::DeviceRadixSort::SortPairsDescending(
        tmp, temp_bytes, kin, kout, vin, vout, NPROP, 0, 32, (cudaStream_t)0);

    // 3) gather top-6000 boxes
    gather_kernel<<<KPAD / 128, 128>>>();

    // 4) suppression bitmask (upper triangle only)
    dim3 mg(WORDS, KPAD / 128);
    mask_kernel<<<mg, 128>>>();

    // 5) exact greedy NMS scan with early stop
    nms_scan_kernel<<<1, 192>>>();

    // 6) select + output
    select_kernel<<<1, 192>>>(out);
}

// round 3
// speedup vs baseline: 3.3566x; 1.0462x over previous
#include <cuda_runtime.h>
#include <cuda_bf16.h>
#include <cstdint>
#include <math.h>

// ---------------------------------------------------------------------------
// RoiProposal: RPN proposal layer (softmax -> box decode -> top6000 -> NMS -> top300)
// ---------------------------------------------------------------------------

#define NPROP 36864      // 64*64*9 anchors
#define KTOP  6000       // PRE_NMS_TOPN
#define KPAD  6016       // KTOP padded to multiple of 32
#define WORDS 188        // KPAD/32
#define TILES 188
#define NOUT  300
#define NBIN  16384      // score-key histogram bins (key >> 18)
#define CAP   16384      // survivor capacity
#define CHUNK 36         // NPROP / 1024

// ------------------------------ scratch (static, allocation-free) -----------
__device__ unsigned g_skey[NPROP];         // monotonic score keys
__device__ int      g_hist[NBIN];
__device__ unsigned g_kS[CAP];             // survivor keys (index-ascending order)
__device__ int      g_iS[CAP];             // survivor original indices
__device__ int      g_rank[CAP];
__device__ int      g_S;
__device__ int      g_tbin;

__device__ float g_px1[NPROP], g_py1[NPROP], g_px2[NPROP], g_py2[NPROP];
__device__ float g_tx1[KPAD], g_ty1[KPAD], g_tx2[KPAD], g_ty2[KPAD], g_ta[KPAD];
__device__ unsigned g_maskT[(size_t)WORDS * KPAD];   // column-word-major: [word][row]
__device__ unsigned g_removed[WORDS];
__device__ int g_stoptile;

// base anchor widths/heights (py-faster-rcnn generate_anchors, exact integers)
__constant__ float c_AW[9] = {184.f, 368.f, 736.f, 128.f, 256.f, 512.f, 88.f, 176.f, 352.f};
__constant__ float c_AH[9] = {96.f, 192.f, 384.f, 128.f, 256.f, 512.f, 176.f, 352.f, 704.f};

// ------------------------------ 0) zero + pads -------------------------------
__global__ void zero_kernel() {
    int i = blockIdx.x * blockDim.x + threadIdx.x;   // 0..16383
    if (i < NBIN) g_hist[i] = 0;
    if (i < CAP)  g_rank[i] = 0;
    if (i >= KTOP && i < KPAD) {                      // pad rows for NMS
        g_tx1[i] = -1e8f; g_ty1[i] = -1e8f; g_tx2[i] = -1e8f; g_ty2[i] = -1e8f;
        g_ta[i] = 1.f;
    }
}

// ------------------------------ 1) proposals + keys + histogram --------------
__global__ void proposal_kernel(const float* __restrict__ cls,
                                const float* __restrict__ bbox) {
    int i = blockIdx.x * blockDim.x + threadIdx.x;
    if (i >= NPROP) return;

    int a = i % 9;
    int cell = i / 9;
    float axc = (float)((cell % 64) * 16 + 8);
    float ayc = (float)((cell / 64) * 16 + 8);
    float aw = c_AW[a];
    float ah = c_AH[a];

    const float* cp = cls + cell * 18 + a * 2;
    float s0 = cp[0], s1 = cp[1];
    const float* dp = bbox + cell * 36 + a * 4;
    float dx = dp[0], dy = dp[1], dw = dp[2], dh = dp[3];

    // box decode — explicit .rn ops (no FMA contraction; match XLA codegen)
    float pxc = __fadd_rn(__fmul_rn(dx, aw), axc);
    float pyc = __fadd_rn(__fmul_rn(dy, ah), ayc);
    float pw  = __fmul_rn(expf(dw), aw);
    float ph  = __fmul_rn(expf(dh), ah);
    float hx  = __fmul_rn(0.5f, pw);
    float hy  = __fmul_rn(0.5f, ph);
    float x1 = fminf(fmaxf(__fsub_rn(pxc, hx), 0.f), 1023.f);
    float x2 = fminf(fmaxf(__fadd_rn(pxc, hx), 0.f), 1023.f);
    float y1 = fminf(fmaxf(__fsub_rn(pyc, hy), 0.f), 1023.f);
    float y2 = fminf(fmaxf(__fadd_rn(pyc, hy), 0.f), 1023.f);

    bool valid = (__fadd_rn(__fsub_rn(x2, x1), 1.f) >= 16.f) &&
                 (__fadd_rn(__fsub_rn(y2, y1), 1.f) >= 16.f);

    float m  = fmaxf(s0, s1);
    float e0 = expf(__fsub_rn(s0, m));
    float e1 = expf(__fsub_rn(s1, m));
    float sc = __fdiv_rn(e1, __fadd_rn(e0, e1));
    if (!valid) sc = -INFINITY;

    g_px1[i] = x1; g_py1[i] = y1; g_px2[i] = x2; g_py2[i] = y2;

    // monotonic float->uint
    unsigned ub = __float_as_uint(sc);
    ub = (ub & 0x80000000u) ? ~ub : (ub | 0x80000000u);
    g_skey[i] = ub;
    atomicAdd(&g_hist[ub >> 18], 1);
}

// ------------------------------ 2) threshold + ordered compaction ------------
// One block, 1024 threads. Finds the smallest set of top bins with >= KTOP keys,
// then compacts all members in ORIGINAL INDEX ORDER (=> stable ties).
__global__ void select_topk_kernel() {
    int t = threadIdx.x;
    __shared__ int s[1024];
    __shared__ int s_tb;

    // suffix sums from the top: thread t covers bins [16383-16t-15 .. 16383-16t]
    int base = 16383 - t * 16;
    int sum = 0;
    #pragma unroll
    for (int k = 0; k < 16; k++) sum += g_hist[base - k];
    s[t] = sum; __syncthreads();
    for (int off = 1; off < 1024; off <<= 1) {
        int v = (t >= off) ? s[t - off] : 0;
        __syncthreads(); s[t] += v; __syncthreads();
    }
    int before = s[t] - sum;         // count in bins strictly above my chunk
    if (before < KTOP && s[t] >= KTOP) {   // crossing happens inside my chunk
        int cum = before;
        #pragma unroll
        for (int k = 0; k < 16; k++) {
            cum += g_hist[base - k];
            if (cum >= KTOP) { s_tb = base - k; break; }
        }
    }
    __syncthreads();
    unsigned tb = (unsigned)s_tb;

    // ordered compaction: thread t owns contiguous items [t*36, t*36+36)
    int st = t * CHUNK;
    int cnt = 0;
    #pragma unroll
    for (int k = 0; k < CHUNK; k++) cnt += ((g_skey[st + k] >> 18) >= tb);
    s[t] = cnt; __syncthreads();
    for (int off = 1; off < 1024; off <<= 1) {
        int v = (t >= off) ? s[t - off] : 0;
        __syncthreads(); s[t] += v; __syncthreads();
    }
    int o = s[t] - cnt;
    #pragma unroll
    for (int k = 0; k < CHUNK; k++) {
        unsigned key = g_skey[st + k];
        if ((key >> 18) >= tb) { g_kS[o] = key; g_iS[o] = st + k; o++; }
    }
    if (t == 1023) { g_S = s[1023]; g_tbin = (int)tb; }
}

// ------------------------------ 3) exact pairwise ranking --------------------
// rank_i = #{j : kj > ki} + #{j < i : kj == ki}  (compaction order = index asc)
__global__ void rank_kernel() {
    __shared__ unsigned sk[1024];
    int S = g_S;
    int jb = blockIdx.y * 1024;
    if (jb >= S) return;
    for (int jj = threadIdx.x; jj < 1024; jj += 256)
        sk[jj] = (jb + jj < S) ? g_kS[jb + jj] : 0u;   // 0 < any real key
    __syncthreads();
    int i = blockIdx.x * 256 + threadIdx.x;
    if (i >= S) return;
    unsigned ki = g_kS[i];
    int jmax = min(1024, S - jb);
    int cnt = 0;
    int jj = 0;
    for (; jj + 4 <= jmax; jj += 4) {
        #pragma unroll
        for (int u = 0; u < 4; u++) {
            unsigned kj = sk[jj + u];
            cnt += (kj > ki) || ((kj == ki) && (jb + jj + u < i));
        }
    }
    for (; jj < jmax; jj++) {
        unsigned kj = sk[jj];
        cnt += (kj > ki) || ((kj == ki) && (jb + jj < i));
    }
    if (cnt) atomicAdd(&g_rank[i], cnt);
}

// ------------------------------ 4) scatter boxes to sorted slots -------------
__global__ void scatter_kernel() {
    int S = g_S;
    int i = blockIdx.x * 256 + threadIdx.x;
    if (i >= S) return;
    int r = g_rank[i];
    if (r < KTOP) {
        int idx = g_iS[i];
        float x1 = g_px1[idx], y1 = g_py1[idx], x2 = g_px2[idx], y2 = g_py2[idx];
        g_tx1[r] = x1; g_ty1[r] = y1; g_tx2[r] = x2; g_ty2[r] = y2;
        g_ta[r] = __fmul_rn(__fadd_rn(__fsub_rn(x2, x1), 1.f),
                            __fadd_rn(__fsub_rn(y2, y1), 1.f));
    }
}

// ------------------------------ 5) IoU suppression bitmask -------------------
__global__ void mask_kernel() {
    int wx = blockIdx.x;                       // 0..187
    if (wx < 4 * (int)blockIdx.y) return;      // below diagonal: never read
    int r  = blockIdx.y * 128 + threadIdx.x;   // 0..6015
    __shared__ float sx1[32], sy1[32], sx2[32], sy2[32], sa[32];
    if (threadIdx.x < 32) {
        int c = wx * 32 + threadIdx.x;
        sx1[threadIdx.x] = g_tx1[c]; sy1[threadIdx.x] = g_ty1[c];
        sx2[threadIdx.x] = g_tx2[c]; sy2[threadIdx.x] = g_ty2[c];
        sa[threadIdx.x]  = g_ta[c];
    }
    __syncthreads();
    unsigned w = 0;
    if (r < KTOP) {
        float x1 = g_tx1[r], y1 = g_ty1[r], x2 = g_tx2[r], y2 = g_ty2[r], ar = g_ta[r];
        #pragma unroll
        for (int b = 0; b < 32; b++) {
            int c = wx * 32 + b;
            float ix1 = fmaxf(x1, sx1[b]);
            float iy1 = fmaxf(y1, sy1[b]);
            float ix2 = fminf(x2, sx2[b]);
            float iy2 = fminf(y2, sy2[b]);
            float iw = fmaxf(__fadd_rn(__fsub_rn(ix2, ix1), 1.f), 0.f);
            float ih = fmaxf(__fadd_rn(__fsub_rn(iy2, iy1), 1.f), 0.f);
            float inter = __fmul_rn(iw, ih);
            float uni = __fsub_rn(__fadd_rn(ar, sa[b]), inter);
            float iou = __fdiv_rn(inter, uni);
            bool bit = (c > r) && (c < KTOP) && (iou > 0.7f);
            w |= ((unsigned)bit) << b;
        }
    }
    if (r < KPAD) g_maskT[(size_t)wx * KPAD + r] = w;
}

// ------------------------------ 6) sequential greedy scan (exact) ------------
__device__ __forceinline__ void load_tile(unsigned (&dst)[32], int t, int T) {
    const uint4* q = reinterpret_cast<const uint4*>(
        &g_maskT[(size_t)t * KPAD + (size_t)T * 32]);
    #pragma unroll
    for (int i = 0; i < 8; i++) {
        uint4 v = q[i];
        dst[4*i+0] = v.x; dst[4*i+1] = v.y; dst[4*i+2] = v.z; dst[4*i+3] = v.w;
    }
}

__device__ __forceinline__ unsigned or_sel(const unsigned (&w)[32], unsigned km) {
    unsigned a0 = 0, a1 = 0, a2 = 0, a3 = 0;
    #pragma unroll
    for (int b = 0; b < 32; b += 4) {
        if (km & (1u << b))       a0 |= w[b];
        if (km & (1u << (b + 1))) a1 |= w[b + 1];
        if (km & (1u << (b + 2))) a2 |= w[b + 2];
        if (km & (1u << (b + 3))) a3 |= w[b + 3];
    }
    return (a0 | a1) | (a2 | a3);
}

__device__ __forceinline__ void diag_resolve(const unsigned (&D)[32], unsigned removed,
                                             unsigned& kept_out) {
    unsigned internal = removed, kept = 0u;
    #pragma unroll
    for (int b = 0; b < 32; b++) {
        if (!((internal >> b) & 1u)) { kept |= (1u << b); internal |= D[b]; }
    }
    kept_out = kept;
}

__global__ void nms_scan_kernel() {
    int t = threadIdx.x;
    bool act = (t < WORDS);
    __shared__ unsigned s_keep[2];
    __shared__ int s_tot[2];
    unsigned D[32], A[32], B[32];
    unsigned removed = 0;

    if (act) load_tile(D, t, t);
    if (act && t >= 1) load_tile(A, t, 0);

    int stop = TILES - 1;
    #pragma unroll 1
    for (int T = 0; T < TILES; T += 2) {
        if (act && t >= T + 2 && T + 1 < TILES) load_tile(B, t, T + 1);
        if (t == T) {
            unsigned kept;
            diag_resolve(D, removed, kept);
            s_keep[0] = kept;
            unsigned cv = (T == TILES - 1) ? (kept & 0xFFFFu) : kept;
            s_tot[0] = ((T == 0) ? 0 : s_tot[1]) + __popc(cv);
        }
        __syncthreads();
        {
            unsigned km = s_keep[0];
            if (act && t >= T) {
                if (t == T) removed |= or_sel(D, km);
                else        removed |= or_sel(A, km);
            }
            if (s_tot[0] >= NOUT) { stop = T; break; }
        }
        if (T + 1 < TILES) {
            if (act && t >= T + 3 && T + 2 < TILES) load_tile(A, t, T + 2);
            if (t == T + 1) {
                unsigned kept;
                diag_resolve(D, removed, kept);
                s_keep[1] = kept;
                unsigned cv = (T + 1 == TILES - 1) ? (kept & 0xFFFFu) : kept;
                s_tot[1] = s_tot[0] + __popc(cv);
            }
            __syncthreads();
            unsigned km = s_keep[1];
            if (act && t >= T + 1) {
                if (t == T + 1) removed |= or_sel(D, km);
                else            removed |= or_sel(B, km);
            }
            if (s_tot[1] >= NOUT) { stop = T + 1; break; }
        }
    }
    if (act) g_removed[t] = removed;
    if (t == 0) g_stoptile = stop;
}

// ------------------------------ 7) select first 300 + write output -----------
__global__ void out_kernel(float* __restrict__ out) {
    int t = threadIdx.x;    // 192 threads
    __shared__ int s[192];
    __shared__ int sidx[NOUT];

    int L = min(KTOP, 32 * (g_stoptile + 1));
    int nb = L - 32 * t;
    nb = nb < 0 ? 0 : (nb > 32 ? 32 : nb);
    unsigned vmask = (nb >= 32) ? 0xFFFFFFFFu : ((nb > 0) ? ((1u << nb) - 1u) : 0u);

    unsigned rem  = (t < WORDS) ? g_removed[t] : 0u;
    unsigned kept = (~rem) & vmask;
    int cnt = __popc(kept);

    s[t] = cnt; __syncthreads();
    for (int off = 1; off < 192; off <<= 1) {
        int v = (t >= off) ? s[t - off] : 0;
        __syncthreads(); s[t] += v; __syncthreads();
    }
    int excl = s[t] - cnt;
    int C = s[191];

    if (excl < NOUT && kept) {
        int r = excl;
        #pragma unroll 4
        for (int b = 0; b < 32; b++) {
            if ((kept >> b) & 1u) {
                if (r < NOUT) sidx[r] = t * 32 + b;
                r++;
            }
        }
    }
    __syncthreads();

    if (C < NOUT) {
        unsigned sup = rem & vmask;
        int cnt2 = __popc(sup);
        s[t] = cnt2; __syncthreads();
        for (int off = 1; off < 192; off <<= 1) {
            int v = (t >= off) ? s[t - off] : 0;
            __syncthreads(); s[t] += v; __syncthreads();
        }
        int base = C + (s[t] - cnt2);
        if (base < NOUT && sup) {
            #pragma unroll 4
            for (int b = 0; b < 32; b++) {
                if ((sup >> b) & 1u) {
                    if (base < NOUT) sidx[base] = t * 32 + b;
                    base++;
                }
            }
        }
        __syncthreads();
    }

    for (int r = t; r < NOUT; r += 192) {
        int idx = sidx[r];
        out[5 * r + 0] = 0.f;
        out[5 * r + 1] = g_tx1[idx];
        out[5 * r + 2] = g_ty1[idx];
        out[5 * r + 3] = g_tx2[idx];
        out[5 * r + 4] = g_ty2[idx];
    }
}

// ------------------------------ launch ---------------------------------------
extern "C" void kernel_launch(void* const* d_in, const int* in_sizes, int n_in,
                              void* d_out, int out_size) {
    const float* cls  = (const float*)d_in[0];   // (1,64,64,18)
    const float* bbox = (const float*)d_in[1];   // (1,64,64,36)
    float* out = (float*)d_out;                  // (300,5)

    zero_kernel<<<NBIN / 256, 256>>>();
    proposal_kernel<<<(NPROP + 255) / 256, 256>>>(cls, bbox);
    select_topk_kernel<<<1, 1024>>>();

    dim3 rg(CAP / 256, CAP / 1024);              // 64 x 16, early-exit on S
    rank_kernel<<<rg, 256>>>();
    scatter_kernel<<<CAP / 256, 256>>>();

    dim3 mg(WORDS, KPAD / 128);
    mask_kernel<<<mg, 128>>>();

    nms_scan_kernel<<<1, 192>>>();
    out_kernel<<<1, 192>>>(out);
}

// round 5
// speedup vs baseline: 3.5257x; 1.0504x over previous
#include <cuda_runtime.h>
#include <cuda_bf16.h>
#include <cstdint>
#include <math.h>

// ---------------------------------------------------------------------------
// RoiProposal: RPN proposal layer (softmax -> box decode -> top6000 -> NMS -> top300)
// ---------------------------------------------------------------------------

#define NPROP 36864      // 64*64*9 anchors
#define KTOP  6000       // PRE_NMS_TOPN
#define KPAD  6016       // KTOP padded to multiple of 32
#define WORDS 188        // KPAD/32
#define TILES 188
#define NOUT  300
#define NBIN  16384      // score-key histogram bins (key >> 18)
#define CAP   16384      // survivor capacity (mult of 1024)
#define CHUNK 36         // NPROP / 1024

// ------------------------------ scratch (static, allocation-free) -----------
__device__ unsigned g_skey[NPROP];              // monotonic score keys
__device__ int      g_hist[NBIN];
__device__ unsigned long long g_k64[CAP];       // survivor (key<<32|~idx), 0-padded
__device__ int      g_iS[CAP];                  // survivor original indices
__device__ int      g_rank[CAP];
__device__ int      g_S;

__device__ float g_px1[NPROP], g_py1[NPROP], g_px2[NPROP], g_py2[NPROP];
__device__ float g_tx1[KPAD], g_ty1[KPAD], g_tx2[KPAD], g_ty2[KPAD], g_ta[KPAD];
__device__ unsigned g_maskT[(size_t)WORDS * KPAD];   // column-word-major: [word][row]
__device__ unsigned g_removed[WORDS];
__device__ int g_stoptile;

// base anchor widths/heights (py-faster-rcnn generate_anchors, exact integers)
__constant__ float c_AW[9] = {184.f, 368.f, 736.f, 128.f, 256.f, 512.f, 88.f, 176.f, 352.f};
__constant__ float c_AH[9] = {96.f, 192.f, 384.f, 128.f, 256.f, 512.f, 176.f, 352.f, 704.f};

// ------------------------------ block scan helper (1024 thr, shuffle) --------
__device__ __forceinline__ int block_incl_scan_1024(int v, int t, int* warpsum) {
    #pragma unroll
    for (int d = 1; d < 32; d <<= 1) {
        int n = __shfl_up_sync(0xFFFFFFFFu, v, d);
        if ((t & 31) >= d) v += n;
    }
    if ((t & 31) == 31) warpsum[t >> 5] = v;
    __syncthreads();
    if (t < 32) {
        int w = warpsum[t];
        #pragma unroll
        for (int d = 1; d < 32; d <<= 1) {
            int n = __shfl_up_sync(0xFFFFFFFFu, w, d);
            if (t >= d) w += n;
        }
        warpsum[t] = w;
    }
    __syncthreads();
    if (t >= 32) v += warpsum[(t >> 5) - 1];
    return v;
}

// ------------------------------ 0) zero + pads -------------------------------
__global__ void zero_kernel() {
    int i = blockIdx.x * blockDim.x + threadIdx.x;   // 0..16383
    if (i < NBIN) g_hist[i] = 0;
    if (i < CAP)  { g_rank[i] = 0; g_k64[i] = 0ull; }
    if (i >= KTOP && i < KPAD) {                      // pad rows for NMS
        g_tx1[i] = -1e8f; g_ty1[i] = -1e8f; g_tx2[i] = -1e8f; g_ty2[i] = -1e8f;
        g_ta[i] = 1.f;
    }
}

// ------------------------------ 1) proposals + keys + histogram --------------
__global__ void proposal_kernel(const float* __restrict__ cls,
                                const float* __restrict__ bbox) {
    int i = blockIdx.x * blockDim.x + threadIdx.x;
    if (i >= NPROP) return;

    int a = i % 9;
    int cell = i / 9;
    float axc = (float)((cell % 64) * 16 + 8);
    float ayc = (float)((cell / 64) * 16 + 8);
    float aw = c_AW[a];
    float ah = c_AH[a];

    const float* cp = cls + cell * 18 + a * 2;
    float s0 = cp[0], s1 = cp[1];
    const float* dp = bbox + cell * 36 + a * 4;
    float dx = dp[0], dy = dp[1], dw = dp[2], dh = dp[3];

    // box decode — explicit .rn ops (no FMA contraction; match XLA codegen)
    float pxc = __fadd_rn(__fmul_rn(dx, aw), axc);
    float pyc = __fadd_rn(__fmul_rn(dy, ah), ayc);
    float pw  = __fmul_rn(expf(dw), aw);
    float ph  = __fmul_rn(expf(dh), ah);
    float hx  = __fmul_rn(0.5f, pw);
    float hy  = __fmul_rn(0.5f, ph);
    float x1 = fminf(fmaxf(__fsub_rn(pxc, hx), 0.f), 1023.f);
    float x2 = fminf(fmaxf(__fadd_rn(pxc, hx), 0.f), 1023.f);
    float y1 = fminf(fmaxf(__fsub_rn(pyc, hy), 0.f), 1023.f);
    float y2 = fminf(fmaxf(__fadd_rn(pyc, hy), 0.f), 1023.f);

    bool valid = (__fadd_rn(__fsub_rn(x2, x1), 1.f) >= 16.f) &&
                 (__fadd_rn(__fsub_rn(y2, y1), 1.f) >= 16.f);

    float m  = fmaxf(s0, s1);
    float e0 = expf(__fsub_rn(s0, m));
    float e1 = expf(__fsub_rn(s1, m));
    float sc = __fdiv_rn(e1, __fadd_rn(e0, e1));
    if (!valid) sc = -INFINITY;

    g_px1[i] = x1; g_py1[i] = y1; g_px2[i] = x2; g_py2[i] = y2;

    unsigned ub = __float_as_uint(sc);
    ub = (ub & 0x80000000u) ? ~ub : (ub | 0x80000000u);
    g_skey[i] = ub;
    atomicAdd(&g_hist[ub >> 18], 1);
}

// ------------------------------ 2) threshold + ordered compaction ------------
// One block, 1024 threads; no big register arrays (re-reads g_skey, L2-hot).
__global__ void __launch_bounds__(1024, 1) select_topk_kernel() {
    int t = threadIdx.x;
    __shared__ int warpsum[32];
    __shared__ int s_tb;
    __shared__ int s_total;

    // suffix sums from the top: thread t covers bins [16383-16t-15 .. 16383-16t]
    int base = 16383 - t * 16;
    int sum = 0;
    #pragma unroll
    for (int k = 0; k < 16; k++) sum += g_hist[base - k];
    int incl = block_incl_scan_1024(sum, t, warpsum);
    int before = incl - sum;
    if (before < KTOP && incl >= KTOP) {
        int cum = before;
        #pragma unroll
        for (int k = 0; k < 16; k++) {
            cum += g_hist[base - k];
            if (cum >= KTOP) { s_tb = base - k; break; }
        }
    }
    __syncthreads();
    unsigned tb = (unsigned)s_tb;

    // ordered compaction: thread t owns contiguous items [t*36, t*36+36)
    int st = t * CHUNK;
    int cnt = 0;
    #pragma unroll
    for (int k = 0; k < CHUNK; k++) cnt += ((g_skey[st + k] >> 18) >= tb);
    __syncthreads();
    int incl2 = block_incl_scan_1024(cnt, t, warpsum);
    int o = incl2 - cnt;
    #pragma unroll
    for (int k = 0; k < CHUNK; k++) {
        unsigned key = g_skey[st + k];
        if ((key >> 18) >= tb) {
            g_k64[o] = ((unsigned long long)key << 32) |
                       (unsigned long long)(0xFFFFFFFFu - (unsigned)(st + k));
            g_iS[o] = st + k;
            o++;
        }
    }
    if (t == 1023) s_total = incl2;
    __syncthreads();
    if (t == 1023) g_S = s_total;
}

// ------------------------------ 3) exact pairwise ranking --------------------
// rank_i = #{j : k64_j > k64_i}  (unique 64-bit keys encode (score desc, idx asc))
__global__ void rank_kernel() {
    __shared__ unsigned long long sk[1024];
    int S = g_S;
    int jb = blockIdx.y << 10;
    if (jb >= S) return;
    #pragma unroll
    for (int u = 0; u < 4; u++)
        sk[threadIdx.x + 256 * u] = g_k64[jb + threadIdx.x + 256 * u];
    __syncthreads();
    int i = blockIdx.x * 256 + threadIdx.x;
    if (i >= S) return;
    unsigned long long ki = g_k64[i];
    int c0 = 0, c1 = 0, c2 = 0, c3 = 0;
    #pragma unroll 4
    for (int jj = 0; jj < 1024; jj += 4) {      // pad entries are 0: never > ki
        c0 += (sk[jj + 0] > ki);
        c1 += (sk[jj + 1] > ki);
        c2 += (sk[jj + 2] > ki);
        c3 += (sk[jj + 3] > ki);
    }
    int cnt = (c0 + c1) + (c2 + c3);
    if (cnt) atomicAdd(&g_rank[i], cnt);
}

// ------------------------------ 4) scatter boxes to sorted slots -------------
__global__ void scatter_kernel() {
    int S = g_S;
    int i = blockIdx.x * 256 + threadIdx.x;
    if (i >= S) return;
    int r = g_rank[i];
    if (r < KTOP) {
        int idx = g_iS[i];
        float x1 = g_px1[idx], y1 = g_py1[idx], x2 = g_px2[idx], y2 = g_py2[idx];
        g_tx1[r] = x1; g_ty1[r] = y1; g_tx2[r] = x2; g_ty2[r] = y2;
        g_ta[r] = __fmul_rn(__fadd_rn(__fsub_rn(x2, x1), 1.f),
                            __fadd_rn(__fsub_rn(y2, y1), 1.f));
    }
}

// ------------------------------ 5) IoU suppression bitmask -------------------
__global__ void mask_kernel() {
    int wx = blockIdx.x;                       // 0..187
    if (wx < 4 * (int)blockIdx.y) return;      // below diagonal: never read
    int r  = blockIdx.y * 128 + threadIdx.x;   // 0..6015
    __shared__ float sx1[32], sy1[32], sx2[32], sy2[32], sa[32];
    if (threadIdx.x < 32) {
        int c = wx * 32 + threadIdx.x;
        sx1[threadIdx.x] = g_tx1[c]; sy1[threadIdx.x] = g_ty1[c];
        sx2[threadIdx.x] = g_tx2[c]; sy2[threadIdx.x] = g_ty2[c];
        sa[threadIdx.x]  = g_ta[c];
    }
    __syncthreads();
    unsigned w = 0;
    if (r < KTOP) {
        float x1 = g_tx1[r], y1 = g_ty1[r], x2 = g_tx2[r], y2 = g_ty2[r], ar = g_ta[r];
        #pragma unroll
        for (int b = 0; b < 32; b++) {
            int c = wx * 32 + b;
            float ix1 = fmaxf(x1, sx1[b]);
            float iy1 = fmaxf(y1, sy1[b]);
            float ix2 = fminf(x2, sx2[b]);
            float iy2 = fminf(y2, sy2[b]);
            float iw = fmaxf(__fadd_rn(__fsub_rn(ix2, ix1), 1.f), 0.f);
            float ih = fmaxf(__fadd_rn(__fsub_rn(iy2, iy1), 1.f), 0.f);
            float inter = __fmul_rn(iw, ih);
            float uni = __fsub_rn(__fadd_rn(ar, sa[b]), inter);
            float iou = __fdiv_rn(inter, uni);
            bool bit = (c > r) && (c < KTOP) && (iou > 0.7f);
            w |= ((unsigned)bit) << b;
        }
    }
    if (r < KPAD) g_maskT[(size_t)wx * KPAD + r] = w;
}

// ------------------------------ 6) sequential greedy scan (exact) ------------
__device__ __forceinline__ void load_tile(unsigned (&dst)[32], int t, int T) {
    const uint4* q = reinterpret_cast<const uint4*>(
        &g_maskT[(size_t)t * KPAD + (size_t)T * 32]);
    #pragma unroll
    for (int i = 0; i < 8; i++) {
        uint4 v = q[i];
        dst[4*i+0] = v.x; dst[4*i+1] = v.y; dst[4*i+2] = v.z; dst[4*i+3] = v.w;
    }
}

__device__ __forceinline__ unsigned or_sel(const unsigned (&w)[32], unsigned km) {
    unsigned a0 = 0, a1 = 0, a2 = 0, a3 = 0;
    #pragma unroll
    for (int b = 0; b < 32; b += 4) {
        if (km & (1u << b))       a0 |= w[b];
        if (km & (1u << (b + 1))) a1 |= w[b + 1];
        if (km & (1u << (b + 2))) a2 |= w[b + 2];
        if (km & (1u << (b + 3))) a3 |= w[b + 3];
    }
    return (a0 | a1) | (a2 | a3);
}

__device__ __forceinline__ void diag_resolve(const unsigned (&D)[32], unsigned removed,
                                             unsigned& kept_out) {
    unsigned internal = removed, kept = 0u;
    #pragma unroll
    for (int b = 0; b < 32; b++) {
        if (!((internal >> b) & 1u)) { kept |= (1u << b); internal |= D[b]; }
    }
    kept_out = kept;
}

__global__ void __launch_bounds__(192, 1) nms_scan_kernel() {
    int t = threadIdx.x;
    bool act = (t < WORDS);
    __shared__ unsigned s_keep[2];
    __shared__ int s_tot[2];
    unsigned D[32], A[32], B[32];
    unsigned removed = 0;

    if (act) load_tile(D, t, t);
    if (act && t >= 1) load_tile(A, t, 0);

    int stop = TILES - 1;
    #pragma unroll 1
    for (int T = 0; T < TILES; T += 2) {
        if (act && t >= T + 2 && T + 1 < TILES) load_tile(B, t, T + 1);
        if (t == T) {
            unsigned kept;
            diag_resolve(D, removed, kept);
            s_keep[0] = kept;
            unsigned cv = (T == TILES - 1) ? (kept & 0xFFFFu) : kept;
            s_tot[0] = ((T == 0) ? 0 : s_tot[1]) + __popc(cv);
        }
        __syncthreads();
        {
            unsigned km = s_keep[0];
            if (act && t >= T) {
                if (t == T) removed |= or_sel(D, km);
                else        removed |= or_sel(A, km);
            }
            if (s_tot[0] >= NOUT) { stop = T; break; }
        }
        if (T + 1 < TILES) {
            if (act && t >= T + 3 && T + 2 < TILES) load_tile(A, t, T + 2);
            if (t == T + 1) {
                unsigned kept;
                diag_resolve(D, removed, kept);
                s_keep[1] = kept;
                unsigned cv = (T + 1 == TILES - 1) ? (kept & 0xFFFFu) : kept;
                s_tot[1] = s_tot[0] + __popc(cv);
            }
            __syncthreads();
            unsigned km = s_keep[1];
            if (act && t >= T + 1) {
                if (t == T + 1) removed |= or_sel(D, km);
                else            removed |= or_sel(B, km);
            }
            if (s_tot[1] >= NOUT) { stop = T + 1; break; }
        }
    }
    if (act) g_removed[t] = removed;
    if (t == 0) g_stoptile = stop;
}

// ------------------------------ 7) select first 300 + write output -----------
__global__ void out_kernel(float* __restrict__ out) {
    int t = threadIdx.x;    // 192 threads
    __shared__ int s[192];
    __shared__ int sidx[NOUT];

    int L = min(KTOP, 32 * (g_stoptile + 1));
    int nb = L - 32 * t;
    nb = nb < 0 ? 0 : (nb > 32 ? 32 : nb);
    unsigned vmask = (nb >= 32) ? 0xFFFFFFFFu : ((nb > 0) ? ((1u << nb) - 1u) : 0u);

    unsigned rem  = (t < WORDS) ? g_removed[t] : 0u;
    unsigned kept = (~rem) & vmask;
    int cnt = __popc(kept);

    s[t] = cnt; __syncthreads();
    for (int off = 1; off < 192; off <<= 1) {
        int v = (t >= off) ? s[t - off] : 0;
        __syncthreads(); s[t] += v; __syncthreads();
    }
    int excl = s[t] - cnt;
    int C = s[191];

    if (excl < NOUT && kept) {
        int r = excl;
        #pragma unroll 4
        for (int b = 0; b < 32; b++) {
            if ((kept >> b) & 1u) {
                if (r < NOUT) sidx[r] = t * 32 + b;
                r++;
            }
        }
    }
    __syncthreads();

    if (C < NOUT) {
        unsigned sup = rem & vmask;
        int cnt2 = __popc(sup);
        s[t] = cnt2; __syncthreads();
        for (int off = 1; off < 192; off <<= 1) {
            int v = (t >= off) ? s[t - off] : 0;
            __syncthreads(); s[t] += v; __syncthreads();
        }
        int base = C + (s[t] - cnt2);
        if (base < NOUT && sup) {
            #pragma unroll 4
            for (int b = 0; b < 32; b++) {
                if ((sup >> b) & 1u) {
                    if (base < NOUT) sidx[base] = t * 32 + b;
                    base++;
                }
            }
        }
        __syncthreads();
    }

    for (int r = t; r < NOUT; r += 192) {
        int idx = sidx[r];
        out[5 * r + 0] = 0.f;
        out[5 * r + 1] = g_tx1[idx];
        out[5 * r + 2] = g_ty1[idx];
        out[5 * r + 3] = g_tx2[idx];
        out[5 * r + 4] = g_ty2[idx];
    }
}

// ------------------------------ launch ---------------------------------------
extern "C" void kernel_launch(void* const* d_in, const int* in_sizes, int n_in,
                              void* d_out, int out_size) {
    const float* cls  = (const float*)d_in[0];   // (1,64,64,18)
    const float* bbox = (const float*)d_in[1];   // (1,64,64,36)
    float* out = (float*)d_out;                  // (300,5)

    zero_kernel<<<NBIN / 256, 256>>>();
    proposal_kernel<<<(NPROP + 255) / 256, 256>>>(cls, bbox);
    select_topk_kernel<<<1, 1024>>>();

    dim3 rg(CAP / 256, CAP / 1024);              // 64 x 16, early-exit on S
    rank_kernel<<<rg, 256>>>();
    scatter_kernel<<<CAP / 256, 256>>>();

    dim3 mg(WORDS, KPAD / 128);
    mask_kernel<<<mg, 128>>>();

    nms_scan_kernel<<<1, 192>>>();
    out_kernel<<<1, 192>>>(out);
}